// round 16
// baseline (speedup 1.0000x reference)
#include <cuda_runtime.h>
#include <math.h>

// Problem shape (fixed by reference setup_inputs)
#define BATCH 2048
#define NLABELS 50000
#define NTRIALS 64

// One warp per row. Lanes probe trials 0..7 with 4-way address duplication
// (lane & 7): full-width unpredicated LDG coalescing into only 8 distinct
// lines per row. P(row unresolved after 8 trials) ~ 0.24^8 ~ 1e-5; guarded
// 8-wide fallback rounds over trials 8..63 keep exactness for ANY input.
#define PROBE 8
#define WARPS_PER_BLOCK 8
#define THREADS_PER_BLOCK (WARPS_PER_BLOCK * 32)   // 256
#define NUM_BLOCKS (BATCH / WARPS_PER_BLOCK)       // 256  (best-known envelope)

// Scratch partials (no allocations allowed anywhere).
__device__ float g_partials[NUM_BLOCKS];
// atomicInc with limit NUM_BLOCKS-1 wraps to 0 on the last arrival ->
// counter auto-resets for every graph replay.
__device__ unsigned int g_arrive = 0;

__global__ void __launch_bounds__(THREADS_PER_BLOCK)
warp_loss_fused(const float* __restrict__ inp,
                const int* __restrict__ pos_idx,
                const int* __restrict__ neg_cands,
                float* __restrict__ out)
{
    const int lane = threadIdx.x & 31;
    const int sub  = lane & (PROBE - 1);            // duplicated trial slot
    const int wid  = threadIdx.x >> 5;
    const int row  = blockIdx.x * WARPS_PER_BLOCK + wid;

    const long  base  = (long)row * NLABELS;
    // Full-width unpredicated loads; 4-way duplicated addresses -> 8 distinct
    // random lines per row instead of 32.
    const int   p     = __ldg(pos_idx + row);                    // broadcast
    const int   idx0  = __ldg(neg_cands + row * NTRIALS + sub);  // dup-coalesced
    const float pos_s = __ldg(inp + base + p);                   // 1 line/row
    const float neg0  = __ldg(inp + base + idx0);                // 8 lines/row
    const float thr   = pos_s - 1.0f;               // margin>=0 <=> neg>=thr

    // ---- trials 0..7: ballot, use low-8 bits only ----
    const unsigned m0 = __ballot_sync(0xffffffffu, neg0 >= thr) & 0xFFu;

    float loss = 0.0f;
    if (m0) {
        const int   first = __ffs(m0) - 1;
        const float sel   = __shfl_sync(0xffffffffu, neg0, first);
        if (lane == 0) {
            const float nt = (float)(first + 1);
            const float L  = logf(floorf((float)(NLABELS - 1) / nt));
            loss = L * (1.0f - pos_s + sel);
        }
    } else {
        // ---- fallback rounds: trials 8..63 (P ~ 1e-5 per row) ----
        #pragma unroll 1
        for (int k = 1; k < NTRIALS / PROBE; k++) {
            const int   trial = k * PROBE + sub;
            const int   idx   = __ldg(neg_cands + row * NTRIALS + trial);
            const float neg   = __ldg(inp + base + idx);
            const unsigned m  = __ballot_sync(0xffffffffu, neg >= thr) & 0xFFu;
            if (m) {
                const int   f   = __ffs(m) - 1;
                const float sel = __shfl_sync(0xffffffffu, neg, f);
                if (lane == 0) {
                    const float nt = (float)(k * PROBE + f + 1);
                    const float L  = logf(floorf((float)(NLABELS - 1) / nt));
                    loss = L * (1.0f - pos_s + sel);
                }
                break;
            }
        }
        // no accepted negative anywhere -> loss stays 0 (matches reference)
    }

    // ---- block partial: lane 0 of each warp holds the row loss ----
    __shared__ float s_warp[WARPS_PER_BLOCK];
    __shared__ bool  s_is_last;
    if (lane == 0) s_warp[wid] = loss;
    __syncthreads();
    if (threadIdx.x == 0) {
        float sum = 0.0f;
        #pragma unroll
        for (int i = 0; i < WARPS_PER_BLOCK; i++) sum += s_warp[i];
        g_partials[blockIdx.x] = sum;
        __threadfence();                      // partial visible GPU-wide
        unsigned old = atomicInc(&g_arrive, NUM_BLOCKS - 1);  // wraps -> reset
        s_is_last = (old == NUM_BLOCKS - 1);
    }
    __syncthreads();

    // Last-arriving block, warp 0: fixed-order sum of 256 partials (L2-hot).
    if (s_is_last && wid == 0) {
        float v = 0.0f;
        #pragma unroll
        for (int j = 0; j < NUM_BLOCKS / 32; j++)
            v += g_partials[lane + j * 32];
        #pragma unroll
        for (int off = 16; off >= 1; off >>= 1)
            v += __shfl_xor_sync(0xffffffffu, v, off);
        if (lane == 0) out[0] = v;
    }
}

extern "C" void kernel_launch(void* const* d_in, const int* in_sizes, int n_in,
                              void* d_out, int out_size)
{
    // metadata order: input (f32 [B,Y]), target (i32, UNUSED), pos_idx (i32 [B]),
    //                 neg_cands (i32 [B,T]); output f32 [1]
    const float* inp     = (const float*)d_in[0];
    const int*   pos_idx = (const int*)d_in[2];
    const int*   neg     = (const int*)d_in[3];
    float*       out     = (float*)d_out;

    warp_loss_fused<<<NUM_BLOCKS, THREADS_PER_BLOCK>>>(inp, pos_idx, neg, out);
}